// round 17
// baseline (speedup 1.0000x reference)
#include <cuda_runtime.h>
#include <cuda_fp16.h>
#include <cstdint>

// R17 = R16 + threefry g1 rotations moved to the fma pipe:
//   rot(b,sh)^a  ==  lop3((b*2^sh).lo, (b*2^sh).hi, a, 0x56)
// with 2 full-rate 32-bit IMADs (mul.lo/mul.hi) + ONE fused LOP3.
// Multipliers loaded from a __device__ global so ptxas can't strength-reduce.
// alu-locked ops/mask: 41 -> 33 (floor 679 -> ~550 us). Bit-exact masks.
// B=1, S=4096, H=16, D=64. BM=128 (8 warps x 16 rows), BN=64 keys/tile.

#define NSEQ 4096
#define NHEAD 16

// half-element offsets in dynamic smem (32KB total)
#define SQ 0
#define SK 8192
#define SV 12288
#define SMEM_BYTES (16384 * 2)

// opaque rotation multipliers for g1 (17, 29, 16, 24)
__device__ uint32_t G1M[4] = {1u << 17, 1u << 29, 1u << 16, 1u << 24};

// ---------------- threefry2x32, key (0,42), draw = bits1 ^ bits2 ----------------
__device__ __forceinline__ void tf_g0(uint32_t& a, uint32_t& b) {
    a += b; b = __funnelshift_l(b, b, 13); b ^= a;
    a += b; b = __funnelshift_l(b, b, 15); b ^= a;
    a += b; b = __funnelshift_l(b, b, 26); b ^= a;
    a += b; b = __funnelshift_l(b, b, 6);  b ^= a;
}
// rot(b)^a via fma-pipe muls + one fused LOP3 ((lo|hi)^a -> lut 0x56)
__device__ __forceinline__ uint32_t rotm(uint32_t b, uint32_t a, uint32_t m) {
    uint32_t lo, hi, r;
    asm("mul.lo.u32 %0, %1, %2;" : "=r"(lo) : "r"(b), "r"(m));
    asm("mul.hi.u32 %0, %1, %2;" : "=r"(hi) : "r"(b), "r"(m));
    asm("lop3.b32 %0, %1, %2, %3, 0x56;" : "=r"(r) : "r"(lo), "r"(hi), "r"(a));
    return r;
}
__device__ __forceinline__ void tf_g1m(uint32_t& a, uint32_t& b, const uint4& m) {
    a += b; b = rotm(b, a, m.x);
    a += b; b = rotm(b, a, m.y);
    a += b; b = rotm(b, a, m.z);
    a += b; b = rotm(b, a, m.w);
}
__device__ __forceinline__ uint32_t keep_mask(uint32_t e, const uint4& m) {
    uint32_t a = 0u;
    uint32_t b = e + 42u;
    tf_g0(a, b);     a += 42u;          b += 0x1BD11BF1u;
    tf_g1m(a, b, m); a += 0x1BD11BF0u;  b += 2u;
    tf_g0(a, b);                        b += 45u;
    tf_g1m(a, b, m); a += 42u;          b += 0x1BD11BF4u;
    tf_g0(a, b);     a += 0x1BD11BF0u;  b += 5u;
    // (x>>9) < 7549747  <=>  x < 7549747*512 (bit-exact)
    return ((a ^ b) < 3865470464u) ? 1u : 0u;
}

// ---------------- smem swizzle: 64-half rows (128B), XOR 16B-chunk swizzle ----------------
__device__ __forceinline__ int swz(int row, int col) {
    return (row << 6) + ((((col >> 3) ^ (row & 7)) << 3) | (col & 7));
}
__device__ __forceinline__ uint32_t sptr(const void* p) {
    return (uint32_t)__cvta_generic_to_shared(p);
}
__device__ __forceinline__ void ldsm4(uint32_t& r0, uint32_t& r1, uint32_t& r2, uint32_t& r3, uint32_t a) {
    asm volatile("ldmatrix.sync.aligned.m8n8.x4.shared.b16 {%0,%1,%2,%3}, [%4];"
                 : "=r"(r0), "=r"(r1), "=r"(r2), "=r"(r3) : "r"(a));
}
__device__ __forceinline__ void ldsm4t(uint32_t& r0, uint32_t& r1, uint32_t& r2, uint32_t& r3, uint32_t a) {
    asm volatile("ldmatrix.sync.aligned.m8n8.x4.trans.shared.b16 {%0,%1,%2,%3}, [%4];"
                 : "=r"(r0), "=r"(r1), "=r"(r2), "=r"(r3) : "r"(a));
}
__device__ __forceinline__ void mma16816(float* c, const uint32_t* a, uint32_t b0, uint32_t b1) {
    asm volatile(
        "mma.sync.aligned.m16n8k16.row.col.f32.f16.f16.f32 "
        "{%0,%1,%2,%3},{%4,%5,%6,%7},{%8,%9},{%0,%1,%2,%3};"
        : "+f"(c[0]), "+f"(c[1]), "+f"(c[2]), "+f"(c[3])
        : "r"(a[0]), "r"(a[1]), "r"(a[2]), "r"(a[3]), "r"(b0), "r"(b1));
}
__device__ __forceinline__ uint32_t cvt_h2(float x, float y) {
    __half2 h = __floats2half2_rn(x, y);
    return *reinterpret_cast<uint32_t*>(&h);
}
__device__ __forceinline__ float ex2(float x) {
    float y;
    asm("ex2.approx.ftz.f32 %0, %1;" : "=f"(y) : "f"(x));
    return y;
}

__global__ void __launch_bounds__(256, 2)
attn_mma(const float* __restrict__ q, const float* __restrict__ k,
         const float* __restrict__ v, float* __restrict__ out)
{
    extern __shared__ __align__(16) __half SH[];
    __half* Ks = SH + SK;
    __half* Vs = SH + SV;

    const int tid = threadIdx.x;
    const int wid = tid >> 5;
    const int lane = tid & 31;
    const int qd = lane & 3;
    const int h = blockIdx.y;
    const int iBase = blockIdx.x * 128;

    // opaque rotation multipliers (cannot be strength-reduced by ptxas)
    const uint4 g1m = *reinterpret_cast<const uint4*>(G1M);

    // ---- stage Q (fp32 -> plain fp16) into dedicated smem (persistent) ----
#pragma unroll
    for (int it = 0; it < 8; it++) {
        int pos = tid + it * 256;          // 0..2047 float4s
        int row = pos >> 4;                // 0..127
        int c4 = pos & 15;
        float4 g = *reinterpret_cast<const float4*>(q + (size_t)(iBase + row) * 1024 + h * 64 + c4 * 4);
        int idx = swz(row, c4 * 4);
        *reinterpret_cast<uint2*>(&SH[SQ + idx]) =
            make_uint2(cvt_h2(g.x, g.y), cvt_h2(g.z, g.w));
    }

    float o[8][4];
#pragma unroll
    for (int nt = 0; nt < 8; nt++)
#pragma unroll
        for (int c = 0; c < 4; c++) o[nt][c] = 0.0f;
    float lp0 = 0.0f, lp1 = 0.0f;

    const int n0 = iBase + 16 * wid + (lane >> 2);
    const uint32_t eb0 = ((uint32_t)h << 24) | ((uint32_t)n0 << 12);
    const uint32_t eb1 = eb0 + (8u << 12);
    const float C = 0.18033688011112042f;   // 0.125 * log2(e)
    const int qrow = 16 * wid + (lane & 15);
    const int qcsel = (lane >> 4) << 3;

    for (int t = 0; t < 64; t++) {
        const int j0 = t * 64;

        __syncthreads();   // previous tile's K/V reads done (and Q staging at t=0)

        // ---- stage K and V (plain fp16) into smem ----
#pragma unroll
        for (int it = 0; it < 4; it++) {
            int pos = tid + it * 256;
            int row = pos >> 4;
            int c4 = pos & 15;
            size_t goff = (size_t)(j0 + row) * 1024 + h * 64 + c4 * 4;
            float4 kg = *reinterpret_cast<const float4*>(k + goff);
            float4 vg = *reinterpret_cast<const float4*>(v + goff);
            int idx = swz(row, c4 * 4);
            *reinterpret_cast<uint2*>(&Ks[idx]) =
                make_uint2(cvt_h2(kg.x, kg.y), cvt_h2(kg.z, kg.w));
            *reinterpret_cast<uint2*>(&Vs[idx]) =
                make_uint2(cvt_h2(vg.x, vg.y), cvt_h2(vg.z, vg.w));
        }
        __syncthreads();

        // ---- dropout masks: 32 independent threefry chains, batched for ILP ----
        uint32_t mask = 0;
#pragma unroll
        for (int nt = 0; nt < 8; nt++) {
            uint32_t jb = (uint32_t)(j0 + 8 * nt + 2 * qd);
            mask |= keep_mask(eb0 + jb, g1m)      << (4 * nt);
            mask |= keep_mask(eb0 + jb + 1u, g1m) << (4 * nt + 1);
            mask |= keep_mask(eb1 + jb, g1m)      << (4 * nt + 2);
            mask |= keep_mask(eb1 + jb + 1u, g1m) << (4 * nt + 3);
        }

        // ---- MMA1: S = Q K^T (plain fp16) ----
        float s[8][4];
#pragma unroll
        for (int nt = 0; nt < 8; nt++)
#pragma unroll
            for (int c = 0; c < 4; c++) s[nt][c] = 0.0f;

#pragma unroll
        for (int kp = 0; kp < 2; kp++) {
            uint32_t qh0[4], qh1[4];
            int c0 = (2 * kp) * 16 + qcsel;
            int c1 = (2 * kp + 1) * 16 + qcsel;
            ldsm4(qh0[0], qh0[1], qh0[2], qh0[3], sptr(&SH[SQ + swz(qrow, c0)]));
            ldsm4(qh1[0], qh1[1], qh1[2], qh1[3], sptr(&SH[SQ + swz(qrow, c1)]));
#pragma unroll
            for (int nt = 0; nt < 8; nt++) {
                int brow = 8 * nt + (lane & 7);
                int bcol = 32 * kp + (lane & 24);
                uint32_t bh0, bh1, bh2, bh3;
                ldsm4(bh0, bh1, bh2, bh3, sptr(&Ks[swz(brow, bcol)]));
                mma16816(s[nt], qh0, bh0, bh1);
                mma16816(s[nt], qh1, bh2, bh3);
            }
        }

        // ---- epilogue: exp, apply mask bits, pack P to plain fp16 A-frags ----
        uint32_t ah[4][4];
#pragma unroll
        for (int nt = 0; nt < 8; nt++) {
            float p00 = ex2(s[nt][0] * C);
            float p01 = ex2(s[nt][1] * C);
            float p10 = ex2(s[nt][2] * C);
            float p11 = ex2(s[nt][3] * C);
            lp0 += p00 + p01;
            lp1 += p10 + p11;
            if (!((mask >> (4 * nt)) & 1u))     p00 = 0.0f;
            if (!((mask >> (4 * nt + 1)) & 1u)) p01 = 0.0f;
            if (!((mask >> (4 * nt + 2)) & 1u)) p10 = 0.0f;
            if (!((mask >> (4 * nt + 3)) & 1u)) p11 = 0.0f;
            int kk2 = nt >> 1, sel = (nt & 1) * 2;
            ah[kk2][sel + 0] = cvt_h2(p00, p01);
            ah[kk2][sel + 1] = cvt_h2(p10, p11);
        }

        // ---- MMA2: O += P V (both plain fp16) ----
#pragma unroll
        for (int nt = 0; nt < 8; nt++) {
            int bcol = 8 * nt;
#pragma unroll
            for (int kp = 0; kp < 2; kp++) {
                int brow = 32 * kp + lane;
                uint32_t vh0, vh1, vh2, vh3;
                ldsm4t(vh0, vh1, vh2, vh3, sptr(&Vs[swz(brow, bcol)]));
                mma16816(o[nt], ah[2 * kp], vh0, vh1);
                mma16816(o[nt], ah[2 * kp + 1], vh2, vh3);
            }
        }
    }

    // row-sum reduction within each quad (same row, 4 threads over columns)
    lp0 += __shfl_xor_sync(0xffffffffu, lp0, 1);
    lp0 += __shfl_xor_sync(0xffffffffu, lp0, 2);
    lp1 += __shfl_xor_sync(0xffffffffu, lp1, 1);
    lp1 += __shfl_xor_sync(0xffffffffu, lp1, 2);
    const float inv0 = 1.0f / (lp0 * 0.9f);
    const float inv1 = 1.0f / (lp1 * 0.9f);

    // scatter per reference reshape chain: out[((n&255)*16+h)*1024 + (n>>8)*64 + dv]
    const int n1 = n0 + 8;
    float* ob0 = out + (size_t)((n0 & 255) * 16 + h) * 1024 + (n0 >> 8) * 64;
    float* ob1 = out + (size_t)((n1 & 255) * 16 + h) * 1024 + (n1 >> 8) * 64;
#pragma unroll
    for (int nt = 0; nt < 8; nt++) {
        int dv = 8 * nt + 2 * qd;
        *reinterpret_cast<float2*>(ob0 + dv) = make_float2(o[nt][0] * inv0, o[nt][1] * inv0);
        *reinterpret_cast<float2*>(ob1 + dv) = make_float2(o[nt][2] * inv1, o[nt][3] * inv1);
    }
}

extern "C" void kernel_launch(void* const* d_in, const int* in_sizes, int n_in,
                              void* d_out, int out_size)
{
    const float* q = (const float*)d_in[0];
    const float* k = (const float*)d_in[1];
    const float* v = (const float*)d_in[2];
    float* out = (float*)d_out;
    cudaFuncSetAttribute(attn_mma, cudaFuncAttributeMaxDynamicSharedMemorySize, SMEM_BYTES);
    dim3 grid(NSEQ / 128, NHEAD);
    attn_mma<<<grid, 256, SMEM_BYTES>>>(q, k, v, out);
}